// round 2
// baseline (speedup 1.0000x reference)
#include <cuda_runtime.h>
#include <cstdint>

#define B_   128
#define P_   168
#define HIDC 32
#define CK   6
#define L_   163          // P - CK + 1
#define HIDR 100
#define HIDS 5
#define SKIP 24
#define PT   6
#define KDIM 4032         // P * 24
#define NDIM 32256        // P * HIDC * CK
#define HW_  24
#define M_   24
#define BCH  4096         // B_ * HIDC

typedef unsigned long long ull;

// ---------------- scratch (device globals; no allocation) ----------------
__device__ float d_xr[B_ * KDIM];          // tf32-rounded x
__device__ float d_c[B_ * NDIM];           // conv output (post-relu)
__device__ float d_c2t[L_ * BCH];          // overlap-added, t-major [t][b][ch]
__device__ float d_h1[B_ * HIDR];
__device__ float d_hs[B_ * SKIP * HIDS];

// ---------------- helpers ----------------
__device__ __forceinline__ uint32_t f2tf32(float f) {
    uint32_t u; asm("cvt.rna.tf32.f32 %0, %1;" : "=r"(u) : "f"(f)); return u;
}
__device__ __forceinline__ void mma_tf32(float& c0, float& c1, float& c2, float& c3,
                                         uint32_t a0, uint32_t a1, uint32_t a2, uint32_t a3,
                                         uint32_t b0, uint32_t b1) {
    asm volatile(
        "mma.sync.aligned.m16n8k8.row.col.f32.tf32.tf32.f32 "
        "{%0,%1,%2,%3},{%4,%5,%6,%7},{%8,%9},{%0,%1,%2,%3};"
        : "+f"(c0), "+f"(c1), "+f"(c2), "+f"(c3)
        : "r"(a0), "r"(a1), "r"(a2), "r"(a3), "r"(b0), "r"(b1));
}
__device__ __forceinline__ ull pk2(float lo, float hi) {
    ull r; asm("mov.b64 %0,{%1,%2};" : "=l"(r) : "f"(lo), "f"(hi)); return r;
}
__device__ __forceinline__ void unpk2(ull v, float& lo, float& hi) {
    asm("mov.b64 {%0,%1},%2;" : "=f"(lo), "=f"(hi) : "l"(v));
}
__device__ __forceinline__ ull fma2_(ull a, ull b, ull c) {
    ull d; asm("fma.rn.f32x2 %0,%1,%2,%3;" : "=l"(d) : "l"(a), "l"(b), "l"(c));
    return d;
}
__device__ __forceinline__ float sigmf(float x) { return 1.f / (1.f + __expf(-x)); }
__device__ __forceinline__ float tanhf_(float x) {
    float e = __expf(-2.f * fabsf(x));
    float r = (1.f - e) / (1.f + e);
    return copysignf(r, x);
}

// ---------------- k0: round x to tf32 ----------------
__global__ void k_cvt(const float* __restrict__ x) {
    int i = blockIdx.x * 256 + threadIdx.x;
    if (i < B_ * KDIM) d_xr[i] = __uint_as_float(f2tf32(x[i]));
}

// ---------------- k1: GEMM c = relu(x @ W^T + b) ----------------
// BM=128, BN=256, BK=32; 8 warps (2x4), warp tile 64x64; m16n8k8 tf32.
// SMEM per stage: A 128x36 + W 256x36 floats = 13824 floats; 3 stages.
__global__ void __launch_bounds__(256, 1) k_gemm(const float* __restrict__ W,
                                                 const float* __restrict__ bias) {
    extern __shared__ float sm[];
    const int tid = threadIdx.x;
    const long n0 = (long)blockIdx.x * 256;
    const int lane = tid & 31, warp = tid >> 5;
    const int wm = warp >> 2, wn = warp & 3;
    uint32_t smbase = (uint32_t)__cvta_generic_to_shared(sm);
    const float* gW = W + n0 * KDIM;

    float acc[4][8][4];
#pragma unroll
    for (int i = 0; i < 4; i++)
#pragma unroll
        for (int jj = 0; jj < 8; jj++)
#pragma unroll
            for (int r = 0; r < 4; r++) acc[i][jj][r] = 0.f;

    auto load_tile = [&](int kt, int s) {
        const float* a = d_xr + kt * 32;
        const float* w = gW + kt * 32;
        uint32_t sb = smbase + s * 13824 * 4;
#pragma unroll
        for (int i = 0; i < 4; i++) {
            int c = tid + i * 256;
            int row = c >> 3, kq = c & 7;
            asm volatile("cp.async.ca.shared.global [%0],[%1],16;" ::
                         "r"(sb + (row * 36 + kq * 4) * 4),
                         "l"(a + (long)row * KDIM + kq * 4));
        }
#pragma unroll
        for (int i = 0; i < 8; i++) {
            int c = tid + i * 256;
            int n = c >> 3, kq = c & 7;
            asm volatile("cp.async.ca.shared.global [%0],[%1],16;" ::
                         "r"(sb + (4608 + n * 36 + kq * 4) * 4),
                         "l"(w + (long)n * KDIM + kq * 4));
        }
        asm volatile("cp.async.commit_group;");
    };

    load_tile(0, 0);
    load_tile(1, 1);

    for (int kt = 0; kt < 126; ++kt) {
        asm volatile("cp.async.wait_group 1;");
        __syncthreads();
        const float* As = sm + (kt % 3) * 13824;
        const float* Ws = As + 4608;
#pragma unroll
        for (int kk = 0; kk < 32; kk += 8) {
            uint32_t af[4][4];
            uint32_t bf[8][2];
#pragma unroll
            for (int mt = 0; mt < 4; ++mt) {
                int r0 = wm * 64 + mt * 16 + (lane >> 2);
                int c0 = kk + (lane & 3);
                af[mt][0] = __float_as_uint(As[r0 * 36 + c0]);
                af[mt][1] = __float_as_uint(As[(r0 + 8) * 36 + c0]);
                af[mt][2] = __float_as_uint(As[r0 * 36 + c0 + 4]);
                af[mt][3] = __float_as_uint(As[(r0 + 8) * 36 + c0 + 4]);
            }
#pragma unroll
            for (int nt = 0; nt < 8; ++nt) {
                int n = wn * 64 + nt * 8 + (lane >> 2);
                int k = kk + (lane & 3);
                bf[nt][0] = f2tf32(Ws[n * 36 + k]);
                bf[nt][1] = f2tf32(Ws[n * 36 + k + 4]);
            }
#pragma unroll
            for (int mt = 0; mt < 4; ++mt)
#pragma unroll
                for (int nt = 0; nt < 8; ++nt)
                    mma_tf32(acc[mt][nt][0], acc[mt][nt][1], acc[mt][nt][2], acc[mt][nt][3],
                             af[mt][0], af[mt][1], af[mt][2], af[mt][3],
                             bf[nt][0], bf[nt][1]);
        }
        __syncthreads();
        if (kt + 2 < 126) load_tile(kt + 2, (kt + 2) % 3);
        else asm volatile("cp.async.commit_group;");
    }

#pragma unroll
    for (int mt = 0; mt < 4; ++mt) {
        int row = wm * 64 + mt * 16 + (lane >> 2);
#pragma unroll
        for (int nt = 0; nt < 8; ++nt) {
            long col = n0 + wn * 64 + nt * 8 + 2 * (lane & 3);
            float b0 = bias[col], b1 = bias[col + 1];
            float2 v0 = {fmaxf(acc[mt][nt][0] + b0, 0.f), fmaxf(acc[mt][nt][1] + b1, 0.f)};
            float2 v1 = {fmaxf(acc[mt][nt][2] + b0, 0.f), fmaxf(acc[mt][nt][3] + b1, 0.f)};
            *(float2*)&d_c[(long)row * NDIM + col] = v0;
            *(float2*)&d_c[(long)(row + 8) * NDIM + col] = v1;
        }
    }
}

// ---------------- k2: overlap-add to t-major c2t ----------------
// block = b*32+ch; thread t<163: c2t[t][b][ch] = sum_k c[b][ch*1008 + k*169 + t]
__global__ void k_overlap() {
    int bc = blockIdx.x;           // b*32 + ch
    int b = bc >> 5, ch = bc & 31;
    int t = threadIdx.x;
    if (t >= L_) return;
    const float* cb = d_c + (long)b * NDIM + ch * (CK * P_);
    float s = 0.f;
#pragma unroll
    for (int k = 0; k < CK; k++) s += cb[k * (P_ + 1) + t];
    d_c2t[t * BCH + bc] = s;
}

// ---------------- k3: GRU1 (blocks 0..127) + skip GRU (blocks 128..143) ----
__global__ void __launch_bounds__(320, 1) k_gru(
    const float* __restrict__ g1Wih, const float* __restrict__ g1Whh,
    const float* __restrict__ g1bih, const float* __restrict__ g1bhh,
    const float* __restrict__ gsWih, const float* __restrict__ gsWhh,
    const float* __restrict__ gsbih, const float* __restrict__ gsbhh) {
    __shared__ __align__(16) float smem_u[704];
    const int bid = blockIdx.x;
    const int j = threadIdx.x;

    if (bid < B_) {
        // ---- GRU1: one batch row per CTA; Whh/Wih rows register-resident ----
        float* h_sh = smem_u;            // [0,100)
        float* x_sh = smem_u + 104;      // [104,168): two 32-float buffers
        float* sh   = smem_u + 168;      // [168,568): rz[200], gin[100], ghn[100]
        ull whh2[50], wih2[16];
        float bih_j = 0.f, bhh_j = 0.f;
        if (j < 300) {
            const ulonglong2* pw = (const ulonglong2*)(g1Whh + j * HIDR);
#pragma unroll
            for (int q = 0; q < 25; q++) { ulonglong2 v = pw[q]; whh2[2*q] = v.x; whh2[2*q+1] = v.y; }
            const ulonglong2* pi = (const ulonglong2*)(g1Wih + j * HIDC);
#pragma unroll
            for (int q = 0; q < 8; q++) { ulonglong2 v = pi[q]; wih2[2*q] = v.x; wih2[2*q+1] = v.y; }
            bih_j = g1bih[j]; bhh_j = g1bhh[j];
        }
        if (j < HIDR) h_sh[j] = 0.f;
        if (j < HIDC) x_sh[j] = d_c2t[bid * HIDC + j];
        float h_reg = 0.f;
        __syncthreads();

        for (int t = 0; t < L_; ++t) {
            float xn = 0.f;
            if (j < HIDC && t + 1 < L_)
                xn = d_c2t[(t + 1) * BCH + bid * HIDC + j];
            const ull* xs = (const ull*)(x_sh + (t & 1) * 32);
            const ull* hs = (const ull*)h_sh;
            if (j < 200) {
                ull a = pk2(bih_j + bhh_j, 0.f);
#pragma unroll
                for (int q = 0; q < 16; q++) a = fma2_(xs[q], wih2[q], a);
#pragma unroll
                for (int q = 0; q < 50; q++) a = fma2_(hs[q], whh2[q], a);
                float lo, hi; unpk2(a, lo, hi);
                sh[j] = lo + hi;
            } else if (j < 300) {
                ull gi = pk2(bih_j, 0.f), gh = pk2(bhh_j, 0.f);
#pragma unroll
                for (int q = 0; q < 16; q++) gi = fma2_(xs[q], wih2[q], gi);
#pragma unroll
                for (int q = 0; q < 50; q++) gh = fma2_(hs[q], whh2[q], gh);
                float lo, hi;
                unpk2(gi, lo, hi); sh[j] = lo + hi;          // gin at [200,300)
                unpk2(gh, lo, hi); sh[j + 100] = lo + hi;    // ghn at [300,400)
            }
            __syncthreads();
            if (j < HIDR) {
                float r = sigmf(sh[j]);
                float z = sigmf(sh[j + 100]);
                float n = tanhf_(sh[j + 200] + r * sh[j + 300]);
                h_reg = (1.f - z) * n + z * h_reg;
                h_sh[j] = h_reg;
            }
            if (j < HIDC) x_sh[((t + 1) & 1) * 32 + j] = xn;
            __syncthreads();
        }
        if (j < HIDR) d_h1[bid * HIDR + j] = h_reg;
    } else {
        // ---- skip GRU: 3072 sequences, one per thread, 6 steps ----
        float* ws = smem_u;  // Wih[480], Whh[75], bih[15], bhh[15]
        for (int i = j; i < 480; i += 320) ws[i] = gsWih[i];
        for (int i = j; i < 75; i += 320) ws[480 + i] = gsWhh[i];
        if (j < 15) { ws[555 + j] = gsbih[j]; ws[570 + j] = gsbhh[j]; }
        __syncthreads();
        if (j < 192) {
            int seq = (bid - B_) * 192 + j;        // = b*SKIP + sk
            int b = seq / SKIP, sk = seq % SKIP;
            float h[5] = {0.f, 0.f, 0.f, 0.f, 0.f};
            for (int pt = 0; pt < PT; ++pt) {
                const float4* xp = (const float4*)(d_c2t + (L_ - PT * SKIP + pt * SKIP + sk) * BCH + b * HIDC);
                float xv[32];
#pragma unroll
                for (int q = 0; q < 8; ++q) {
                    float4 v = xp[q];
                    xv[4*q] = v.x; xv[4*q+1] = v.y; xv[4*q+2] = v.z; xv[4*q+3] = v.w;
                }
                float gi[15], gh[15];
#pragma unroll
                for (int g = 0; g < 15; ++g) {
                    float a = ws[555 + g];
#pragma unroll
                    for (int i2 = 0; i2 < 32; ++i2) a += xv[i2] * ws[g * 32 + i2];
                    gi[g] = a;
                    float bg = ws[570 + g];
#pragma unroll
                    for (int i2 = 0; i2 < 5; ++i2) bg += h[i2] * ws[480 + g * 5 + i2];
                    gh[g] = bg;
                }
#pragma unroll
                for (int q = 0; q < 5; ++q) {
                    float r = sigmf(gi[q] + gh[q]);
                    float z = sigmf(gi[5 + q] + gh[5 + q]);
                    float n = tanhf_(gi[10 + q] + r * gh[10 + q]);
                    h[q] = (1.f - z) * n + z * h[q];
                }
            }
#pragma unroll
            for (int q = 0; q < 5; ++q) d_hs[seq * 5 + q] = h[q];
        }
    }
}

// ---------------- k4: final linear + highway + sigmoid ----------------
__global__ void k_fin(const float* __restrict__ x,
                      const float* __restrict__ lw, const float* __restrict__ lb,
                      const float* __restrict__ hww, const float* __restrict__ hwb,
                      float* __restrict__ out) {
    int b = blockIdx.x, m = threadIdx.x;
    if (m >= M_) return;
    const float* w = lw + m * (HIDR + SKIP * HIDS);
    float a = lb[m];
    const float* h1 = d_h1 + b * HIDR;
#pragma unroll 4
    for (int i = 0; i < HIDR; ++i) a += h1[i] * w[i];
    const float* hsp = d_hs + b * (SKIP * HIDS);
#pragma unroll 4
    for (int i = 0; i < SKIP * HIDS; ++i) a += hsp[i] * w[HIDR + i];
    float z = hwb[0];
#pragma unroll
    for (int wq = 0; wq < HW_; ++wq)
        z += x[b * KDIM + (P_ - HW_ + wq) * M_ + m] * hww[wq];
    out[b * M_ + m] = 1.f / (1.f + __expf(-(a + z)));
}

// ---------------- launch ----------------
extern "C" void kernel_launch(void* const* d_in, const int* in_sizes, int n_in,
                              void* d_out, int out_size) {
    const float* x       = (const float*)d_in[0];
    const float* conv_w  = (const float*)d_in[1];
    const float* conv_b  = (const float*)d_in[2];
    const float* g1Wih   = (const float*)d_in[3];
    const float* g1Whh   = (const float*)d_in[4];
    const float* g1bih   = (const float*)d_in[5];
    const float* g1bhh   = (const float*)d_in[6];
    const float* gsWih   = (const float*)d_in[7];
    const float* gsWhh   = (const float*)d_in[8];
    const float* gsbih   = (const float*)d_in[9];
    const float* gsbhh   = (const float*)d_in[10];
    const float* lin1_w  = (const float*)d_in[11];
    const float* lin1_b  = (const float*)d_in[12];
    const float* hw_w    = (const float*)d_in[13];
    const float* hw_b    = (const float*)d_in[14];
    float* out = (float*)d_out;

    cudaFuncSetAttribute(k_gemm, cudaFuncAttributeMaxDynamicSharedMemorySize, 3 * 13824 * 4);

    k_cvt<<<(B_ * KDIM + 255) / 256, 256>>>(x);
    k_gemm<<<NDIM / 256, 256, 3 * 13824 * 4>>>(conv_w, conv_b);
    k_overlap<<<BCH, 192>>>();
    k_gru<<<B_ + 16, 320>>>(g1Wih, g1Whh, g1bih, g1bhh, gsWih, gsWhh, gsbih, gsbhh);
    k_fin<<<B_, 32>>>(x, lin1_w, lin1_b, hw_w, hw_b, out);
}

// round 3
// speedup vs baseline: 1.0508x; 1.0508x over previous
#include <cuda_runtime.h>
#include <cstdint>

#define B_   128
#define P_   168
#define HIDC 32
#define CK   6
#define L_   163          // P - CK + 1
#define HIDR 100
#define HIDS 5
#define SKIP 24
#define PT   6
#define KDIM 4032         // P * 24
#define NDIM 32256        // P * HIDC * CK
#define HW_  24
#define M_   24
#define BCH  4096         // B_ * HIDC

typedef unsigned long long ull;

// ---------------- scratch (device globals; no allocation) ----------------
__device__ float d_xr[B_ * KDIM];          // tf32-rounded x
__device__ float d_c[B_ * NDIM];           // conv output (post-relu)
__device__ float d_c2t[L_ * BCH];          // overlap-added, t-major [t][b][ch]
__device__ float d_h1[B_ * HIDR];
__device__ float d_hs[B_ * SKIP * HIDS];

// ---------------- helpers ----------------
__device__ __forceinline__ uint32_t f2tf32(float f) {
    uint32_t u; asm("cvt.rna.tf32.f32 %0, %1;" : "=r"(u) : "f"(f)); return u;
}
__device__ __forceinline__ void mma_tf32(float& c0, float& c1, float& c2, float& c3,
                                         uint32_t a0, uint32_t a1, uint32_t a2, uint32_t a3,
                                         uint32_t b0, uint32_t b1) {
    asm volatile(
        "mma.sync.aligned.m16n8k8.row.col.f32.tf32.tf32.f32 "
        "{%0,%1,%2,%3},{%4,%5,%6,%7},{%8,%9},{%0,%1,%2,%3};"
        : "+f"(c0), "+f"(c1), "+f"(c2), "+f"(c3)
        : "r"(a0), "r"(a1), "r"(a2), "r"(a3), "r"(b0), "r"(b1));
}
__device__ __forceinline__ ull pk2(float lo, float hi) {
    ull r; asm("mov.b64 %0,{%1,%2};" : "=l"(r) : "f"(lo), "f"(hi)); return r;
}
__device__ __forceinline__ void unpk2(ull v, float& lo, float& hi) {
    asm("mov.b64 {%0,%1},%2;" : "=f"(lo), "=f"(hi) : "l"(v));
}
__device__ __forceinline__ ull fma2_(ull a, ull b, ull c) {
    ull d; asm("fma.rn.f32x2 %0,%1,%2,%3;" : "=l"(d) : "l"(a), "l"(b), "l"(c));
    return d;
}
__device__ __forceinline__ float sigmf(float x) { return 1.f / (1.f + __expf(-x)); }
__device__ __forceinline__ float tanhf_(float x) {
    float e = __expf(-2.f * fabsf(x));
    float r = (1.f - e) / (1.f + e);
    return copysignf(r, x);
}

// ---------------- k0: round x to tf32 ----------------
__global__ void k_cvt(const float* __restrict__ x) {
    int i = blockIdx.x * 256 + threadIdx.x;
    if (i < B_ * KDIM) d_xr[i] = __uint_as_float(f2tf32(x[i]));
}

// ---------------- k1: GEMM c = relu(x @ W^T + b)  (unchanged) ----------------
__global__ void __launch_bounds__(256, 1) k_gemm(const float* __restrict__ W,
                                                 const float* __restrict__ bias) {
    extern __shared__ float sm[];
    const int tid = threadIdx.x;
    const long n0 = (long)blockIdx.x * 256;
    const int lane = tid & 31, warp = tid >> 5;
    const int wm = warp >> 2, wn = warp & 3;
    uint32_t smbase = (uint32_t)__cvta_generic_to_shared(sm);
    const float* gW = W + n0 * KDIM;

    float acc[4][8][4];
#pragma unroll
    for (int i = 0; i < 4; i++)
#pragma unroll
        for (int jj = 0; jj < 8; jj++)
#pragma unroll
            for (int r = 0; r < 4; r++) acc[i][jj][r] = 0.f;

    auto load_tile = [&](int kt, int s) {
        const float* a = d_xr + kt * 32;
        const float* w = gW + kt * 32;
        uint32_t sb = smbase + s * 13824 * 4;
#pragma unroll
        for (int i = 0; i < 4; i++) {
            int c = tid + i * 256;
            int row = c >> 3, kq = c & 7;
            asm volatile("cp.async.ca.shared.global [%0],[%1],16;" ::
                         "r"(sb + (row * 36 + kq * 4) * 4),
                         "l"(a + (long)row * KDIM + kq * 4));
        }
#pragma unroll
        for (int i = 0; i < 8; i++) {
            int c = tid + i * 256;
            int n = c >> 3, kq = c & 7;
            asm volatile("cp.async.ca.shared.global [%0],[%1],16;" ::
                         "r"(sb + (4608 + n * 36 + kq * 4) * 4),
                         "l"(w + (long)n * KDIM + kq * 4));
        }
        asm volatile("cp.async.commit_group;");
    };

    load_tile(0, 0);
    load_tile(1, 1);

    for (int kt = 0; kt < 126; ++kt) {
        asm volatile("cp.async.wait_group 1;");
        __syncthreads();
        const float* As = sm + (kt % 3) * 13824;
        const float* Ws = As + 4608;
#pragma unroll
        for (int kk = 0; kk < 32; kk += 8) {
            uint32_t af[4][4];
            uint32_t bf[8][2];
#pragma unroll
            for (int mt = 0; mt < 4; ++mt) {
                int r0 = wm * 64 + mt * 16 + (lane >> 2);
                int c0 = kk + (lane & 3);
                af[mt][0] = __float_as_uint(As[r0 * 36 + c0]);
                af[mt][1] = __float_as_uint(As[(r0 + 8) * 36 + c0]);
                af[mt][2] = __float_as_uint(As[r0 * 36 + c0 + 4]);
                af[mt][3] = __float_as_uint(As[(r0 + 8) * 36 + c0 + 4]);
            }
#pragma unroll
            for (int nt = 0; nt < 8; ++nt) {
                int n = wn * 64 + nt * 8 + (lane >> 2);
                int k = kk + (lane & 3);
                bf[nt][0] = f2tf32(Ws[n * 36 + k]);
                bf[nt][1] = f2tf32(Ws[n * 36 + k + 4]);
            }
#pragma unroll
            for (int mt = 0; mt < 4; ++mt)
#pragma unroll
                for (int nt = 0; nt < 8; ++nt)
                    mma_tf32(acc[mt][nt][0], acc[mt][nt][1], acc[mt][nt][2], acc[mt][nt][3],
                             af[mt][0], af[mt][1], af[mt][2], af[mt][3],
                             bf[nt][0], bf[nt][1]);
        }
        __syncthreads();
        if (kt + 2 < 126) load_tile(kt + 2, (kt + 2) % 3);
        else asm volatile("cp.async.commit_group;");
    }

#pragma unroll
    for (int mt = 0; mt < 4; ++mt) {
        int row = wm * 64 + mt * 16 + (lane >> 2);
#pragma unroll
        for (int nt = 0; nt < 8; ++nt) {
            long col = n0 + wn * 64 + nt * 8 + 2 * (lane & 3);
            float b0 = bias[col], b1 = bias[col + 1];
            float2 v0 = {fmaxf(acc[mt][nt][0] + b0, 0.f), fmaxf(acc[mt][nt][1] + b1, 0.f)};
            float2 v1 = {fmaxf(acc[mt][nt][2] + b0, 0.f), fmaxf(acc[mt][nt][3] + b1, 0.f)};
            *(float2*)&d_c[(long)row * NDIM + col] = v0;
            *(float2*)&d_c[(long)(row + 8) * NDIM + col] = v1;
        }
    }
}

// ---------------- k2: overlap-add to t-major c2t ----------------
__global__ void k_overlap() {
    int bc = blockIdx.x;           // b*32 + ch
    int b = bc >> 5, ch = bc & 31;
    int t = threadIdx.x;
    if (t >= L_) return;
    const float* cb = d_c + (long)b * NDIM + ch * (CK * P_);
    float s = 0.f;
#pragma unroll
    for (int k = 0; k < CK; k++) s += cb[k * (P_ + 1) + t];
    d_c2t[t * BCH + bc] = s;
}

// ---------------- k3: GRU1 (blocks 0..127) + skip GRU (blocks 128..143) ----
// GRU1 redesign: uniform per-thread work, pipelined input projection.
//   Thread j<300 per step t:
//     s_j       = bhh_j + Whh_row_j . h          (25 LDS.128, 50 fma2, 4 accums)
//     gi_next_j = bih_j + Wih_row_j . x[t+1]     ( 8 LDS.128, 16 fma2, 2 accums)
//   barrier; thread j<100 combines gi_cur/s into activations, writes h; barrier.
// x for all 163 steps staged in SMEM once via cp.async (20.9 KB).
__global__ void __launch_bounds__(320, 1) k_gru(
    const float* __restrict__ g1Wih, const float* __restrict__ g1Whh,
    const float* __restrict__ g1bih, const float* __restrict__ g1bhh,
    const float* __restrict__ gsWih, const float* __restrict__ gsWhh,
    const float* __restrict__ gsbih, const float* __restrict__ gsbhh) {
    __shared__ __align__(16) float xs[L_ * HIDC];    // 5216 floats
    __shared__ __align__(16) float h_sh[104];
    __shared__ __align__(16) float s_sh[304];
    __shared__ __align__(16) float gi_sh[2][304];
    const int bid = blockIdx.x;
    const int j = threadIdx.x;

    if (bid < B_) {
        // ---- stage x[t][ch] for this batch row: 163 rows of 128B ----
        {
            uint32_t sb = (uint32_t)__cvta_generic_to_shared(xs);
            const float* src = d_c2t + bid * HIDC;
            for (int i = j; i < L_ * 8; i += 320) {
                int t = i >> 3, part = i & 7;
                asm volatile("cp.async.ca.shared.global [%0],[%1],16;" ::
                             "r"(sb + (uint32_t)(t * HIDC + part * 4) * 4),
                             "l"(src + (long)t * BCH + part * 4));
            }
            asm volatile("cp.async.commit_group;");
        }

        // ---- weights register-resident ----
        ull whh2[50], wih2[16];
        float bih_j = 0.f, bhh_j = 0.f;
        if (j < 300) {
            const ulonglong2* pw = (const ulonglong2*)(g1Whh + j * HIDR);
#pragma unroll
            for (int q = 0; q < 25; q++) { ulonglong2 v = pw[q]; whh2[2*q] = v.x; whh2[2*q+1] = v.y; }
            const ulonglong2* pi = (const ulonglong2*)(g1Wih + j * HIDC);
#pragma unroll
            for (int q = 0; q < 8; q++) { ulonglong2 v = pi[q]; wih2[2*q] = v.x; wih2[2*q+1] = v.y; }
            bih_j = g1bih[j]; bhh_j = g1bhh[j];
        }
        if (j < HIDR) h_sh[j] = 0.f;
        asm volatile("cp.async.wait_group 0;");
        __syncthreads();

        // ---- prologue: gi for t=0 ----
        if (j < 300) {
            const ulonglong2* xv = (const ulonglong2*)xs;
            ull g0 = pk2(bih_j, 0.f), g1v = pk2(0.f, 0.f);
#pragma unroll
            for (int q = 0; q < 8; q++) {
                ulonglong2 v = xv[q];
                g0 = fma2_(v.x, wih2[2*q], g0);
                g1v = fma2_(v.y, wih2[2*q+1], g1v);
            }
            float l0, h0, l1, h1;
            unpk2(g0, l0, h0); unpk2(g1v, l1, h1);
            gi_sh[0][j] = (l0 + h0) + (l1 + h1);
        }
        float h_reg = 0.f;
        __syncthreads();

        for (int t = 0; t < L_; ++t) {
            if (j < 300) {
                // s_j = bhh_j + Whh_j . h   (4 accumulators)
                const ulonglong2* h2 = (const ulonglong2*)h_sh;
                ull a0 = pk2(bhh_j, 0.f), a1 = pk2(0.f, 0.f);
                ull a2 = pk2(0.f, 0.f),  a3 = pk2(0.f, 0.f);
#pragma unroll
                for (int q = 0; q < 25; q++) {
                    ulonglong2 hv = h2[q];
                    if (q & 1) {
                        a2 = fma2_(hv.x, whh2[2*q], a2);
                        a3 = fma2_(hv.y, whh2[2*q+1], a3);
                    } else {
                        a0 = fma2_(hv.x, whh2[2*q], a0);
                        a1 = fma2_(hv.y, whh2[2*q+1], a1);
                    }
                }
                float l0, h0, l1, h1, l2, h2f, l3, h3;
                unpk2(a0, l0, h0); unpk2(a1, l1, h1);
                unpk2(a2, l2, h2f); unpk2(a3, l3, h3);
                s_sh[j] = ((l0 + h0) + (l1 + h1)) + ((l2 + h2f) + (l3 + h3));
                // pipeline: gi for t+1
                if (t + 1 < L_) {
                    const ulonglong2* xv = (const ulonglong2*)(xs + (t + 1) * HIDC);
                    ull g0 = pk2(bih_j, 0.f), g1v = pk2(0.f, 0.f);
#pragma unroll
                    for (int q = 0; q < 8; q++) {
                        ulonglong2 v = xv[q];
                        g0 = fma2_(v.x, wih2[2*q], g0);
                        g1v = fma2_(v.y, wih2[2*q+1], g1v);
                    }
                    float gl0, gh0, gl1, gh1;
                    unpk2(g0, gl0, gh0); unpk2(g1v, gl1, gh1);
                    gi_sh[(t + 1) & 1][j] = (gl0 + gh0) + (gl1 + gh1);
                }
            }
            __syncthreads();
            if (j < HIDR) {
                const float* gi = gi_sh[t & 1];
                float r = sigmf(gi[j] + s_sh[j]);
                float z = sigmf(gi[j + 100] + s_sh[j + 100]);
                float n = tanhf_(gi[j + 200] + r * s_sh[j + 200]);
                h_reg = (1.f - z) * n + z * h_reg;
                h_sh[j] = h_reg;
            }
            __syncthreads();
        }
        if (j < HIDR) d_h1[bid * HIDR + j] = h_reg;
    } else {
        // ---- skip GRU: 3072 sequences, one per thread, 6 steps ----
        float* ws = xs;  // reuse pool: Wih[480], Whh[75], bih[15], bhh[15]
        for (int i = j; i < 480; i += 320) ws[i] = gsWih[i];
        for (int i = j; i < 75; i += 320) ws[480 + i] = gsWhh[i];
        if (j < 15) { ws[555 + j] = gsbih[j]; ws[570 + j] = gsbhh[j]; }
        __syncthreads();
        if (j < 192) {
            int seq = (bid - B_) * 192 + j;        // = b*SKIP + sk
            int b = seq / SKIP, sk = seq % SKIP;
            float h[5] = {0.f, 0.f, 0.f, 0.f, 0.f};
            for (int pt = 0; pt < PT; ++pt) {
                const float4* xp = (const float4*)(d_c2t + (L_ - PT * SKIP + pt * SKIP + sk) * BCH + b * HIDC);
                float xv[32];
#pragma unroll
                for (int q = 0; q < 8; ++q) {
                    float4 v = xp[q];
                    xv[4*q] = v.x; xv[4*q+1] = v.y; xv[4*q+2] = v.z; xv[4*q+3] = v.w;
                }
                float gi[15], gh[15];
#pragma unroll
                for (int g = 0; g < 15; ++g) {
                    float a = ws[555 + g];
#pragma unroll
                    for (int i2 = 0; i2 < 32; ++i2) a += xv[i2] * ws[g * 32 + i2];
                    gi[g] = a;
                    float bg = ws[570 + g];
#pragma unroll
                    for (int i2 = 0; i2 < 5; ++i2) bg += h[i2] * ws[480 + g * 5 + i2];
                    gh[g] = bg;
                }
#pragma unroll
                for (int q = 0; q < 5; ++q) {
                    float r = sigmf(gi[q] + gh[q]);
                    float z = sigmf(gi[5 + q] + gh[5 + q]);
                    float n = tanhf_(gi[10 + q] + r * gh[10 + q]);
                    h[q] = (1.f - z) * n + z * h[q];
                }
            }
#pragma unroll
            for (int q = 0; q < 5; ++q) d_hs[seq * 5 + q] = h[q];
        }
    }
}

// ---------------- k4: final linear + highway + sigmoid ----------------
__global__ void k_fin(const float* __restrict__ x,
                      const float* __restrict__ lw, const float* __restrict__ lb,
                      const float* __restrict__ hww, const float* __restrict__ hwb,
                      float* __restrict__ out) {
    int b = blockIdx.x, m = threadIdx.x;
    if (m >= M_) return;
    const float* w = lw + m * (HIDR + SKIP * HIDS);
    float a = lb[m];
    const float* h1 = d_h1 + b * HIDR;
#pragma unroll 4
    for (int i = 0; i < HIDR; ++i) a += h1[i] * w[i];
    const float* hsp = d_hs + b * (SKIP * HIDS);
#pragma unroll 4
    for (int i = 0; i < SKIP * HIDS; ++i) a += hsp[i] * w[HIDR + i];
    float z = hwb[0];
#pragma unroll
    for (int wq = 0; wq < HW_; ++wq)
        z += x[b * KDIM + (P_ - HW_ + wq) * M_ + m] * hww[wq];
    out[b * M_ + m] = 1.f / (1.f + __expf(-(a + z)));
}

// ---------------- launch ----------------
extern "C" void kernel_launch(void* const* d_in, const int* in_sizes, int n_in,
                              void* d_out, int out_size) {
    const float* x       = (const float*)d_in[0];
    const float* conv_w  = (const float*)d_in[1];
    const float* conv_b  = (const float*)d_in[2];
    const float* g1Wih   = (const float*)d_in[3];
    const float* g1Whh   = (const float*)d_in[4];
    const float* g1bih   = (const float*)d_in[5];
    const float* g1bhh   = (const float*)d_in[6];
    const float* gsWih   = (const float*)d_in[7];
    const float* gsWhh   = (const float*)d_in[8];
    const float* gsbih   = (const float*)d_in[9];
    const float* gsbhh   = (const float*)d_in[10];
    const float* lin1_w  = (const float*)d_in[11];
    const float* lin1_b  = (const float*)d_in[12];
    const float* hw_w    = (const float*)d_in[13];
    const float* hw_b    = (const float*)d_in[14];
    float* out = (float*)d_out;

    cudaFuncSetAttribute(k_gemm, cudaFuncAttributeMaxDynamicSharedMemorySize, 3 * 13824 * 4);

    k_cvt<<<(B_ * KDIM + 255) / 256, 256>>>(x);
    k_gemm<<<NDIM / 256, 256, 3 * 13824 * 4>>>(conv_w, conv_b);
    k_overlap<<<BCH, 192>>>();
    k_gru<<<B_ + 16, 320>>>(g1Wih, g1Whh, g1bih, g1bhh, gsWih, gsWhh, gsbih, gsbhh);
    k_fin<<<B_, 32>>>(x, lin1_w, lin1_b, hw_w, hw_b, out);
}

// round 4
// speedup vs baseline: 1.2294x; 1.1700x over previous
#include <cuda_runtime.h>
#include <cstdint>

#define B_   128
#define P_   168
#define HIDC 32
#define CK   6
#define L_   163          // P - CK + 1
#define HIDR 100
#define HIDS 5
#define SKIP 24
#define PT   6
#define KDIM 4032         // P * 24
#define NDIM 32256        // P * HIDC * CK
#define HW_  24
#define M_   24
#define BCH  4096         // B_ * HIDC

#define BN_   224         // GEMM N tile: 144 CTAs exactly
#define STAGE_F 12672     // (128+224)*36 floats per stage

typedef unsigned long long ull;

// ---------------- scratch (device globals; no allocation) ----------------
__device__ float d_xr[B_ * KDIM];          // tf32-rounded x
__device__ float d_c[B_ * NDIM];           // conv output (post-relu)
__device__ float d_c2t[L_ * BCH];          // overlap-added, t-major [t][b][ch]
__device__ float d_h1[B_ * HIDR];
__device__ float d_hs[B_ * SKIP * HIDS];

// ---------------- helpers ----------------
__device__ __forceinline__ uint32_t f2tf32(float f) {
    uint32_t u; asm("cvt.rna.tf32.f32 %0, %1;" : "=r"(u) : "f"(f)); return u;
}
__device__ __forceinline__ void mma_tf32(float& c0, float& c1, float& c2, float& c3,
                                         uint32_t a0, uint32_t a1, uint32_t a2, uint32_t a3,
                                         uint32_t b0, uint32_t b1) {
    asm volatile(
        "mma.sync.aligned.m16n8k8.row.col.f32.tf32.tf32.f32 "
        "{%0,%1,%2,%3},{%4,%5,%6,%7},{%8,%9},{%0,%1,%2,%3};"
        : "+f"(c0), "+f"(c1), "+f"(c2), "+f"(c3)
        : "r"(a0), "r"(a1), "r"(a2), "r"(a3), "r"(b0), "r"(b1));
}
__device__ __forceinline__ ull pk2(float lo, float hi) {
    ull r; asm("mov.b64 %0,{%1,%2};" : "=l"(r) : "f"(lo), "f"(hi)); return r;
}
__device__ __forceinline__ void unpk2(ull v, float& lo, float& hi) {
    asm("mov.b64 {%0,%1},%2;" : "=f"(lo), "=f"(hi) : "l"(v));
}
__device__ __forceinline__ ull fma2_(ull a, ull b, ull c) {
    ull d; asm("fma.rn.f32x2 %0,%1,%2,%3;" : "=l"(d) : "l"(a), "l"(b), "l"(c));
    return d;
}
__device__ __forceinline__ float tanh_ap(float x) {
    float y; asm("tanh.approx.f32 %0,%1;" : "=f"(y) : "f"(x)); return y;
}
__device__ __forceinline__ float sigm_a(float x) {
    return 0.5f * tanh_ap(0.5f * x) + 0.5f;
}

// ---------------- k0: round x to tf32 ----------------
__global__ void k_cvt(const float* __restrict__ x) {
    int i = blockIdx.x * 256 + threadIdx.x;
    if (i < B_ * KDIM) d_xr[i] = __uint_as_float(f2tf32(x[i]));
}

// ---------------- k1: GEMM c = relu(x @ W^T + b) ----------------
// BM=128, BN=224, BK=32; 8 warps (2x4), warp tile 64x56; m16n8k8 tf32.
// W fragment fed raw fp32 bits (HW truncates to tf32) — no cvt in inner loop.
__global__ void __launch_bounds__(256, 1) k_gemm(const float* __restrict__ W,
                                                 const float* __restrict__ bias) {
    extern __shared__ float sm[];
    const int tid = threadIdx.x;
    const long n0 = (long)blockIdx.x * BN_;
    const int lane = tid & 31, warp = tid >> 5;
    const int wm = warp >> 2, wn = warp & 3;
    uint32_t smbase = (uint32_t)__cvta_generic_to_shared(sm);
    const float* gW = W + n0 * KDIM;

    float acc[4][7][4];
#pragma unroll
    for (int i = 0; i < 4; i++)
#pragma unroll
        for (int jj = 0; jj < 7; jj++)
#pragma unroll
            for (int r = 0; r < 4; r++) acc[i][jj][r] = 0.f;

    auto load_tile = [&](int kt, int s) {
        const float* a = d_xr + kt * 32;
        const float* w = gW + kt * 32;
        uint32_t sb = smbase + s * STAGE_F * 4;
#pragma unroll
        for (int i = 0; i < 4; i++) {
            int c = tid + i * 256;
            int row = c >> 3, kq = c & 7;
            asm volatile("cp.async.ca.shared.global [%0],[%1],16;" ::
                         "r"(sb + (row * 36 + kq * 4) * 4),
                         "l"(a + (long)row * KDIM + kq * 4));
        }
#pragma unroll
        for (int i = 0; i < 7; i++) {
            int c = tid + i * 256;
            int n = c >> 3, kq = c & 7;
            asm volatile("cp.async.ca.shared.global [%0],[%1],16;" ::
                         "r"(sb + (4608 + n * 36 + kq * 4) * 4),
                         "l"(w + (long)n * KDIM + kq * 4));
        }
        asm volatile("cp.async.commit_group;");
    };

    load_tile(0, 0);
    load_tile(1, 1);

    for (int kt = 0; kt < 126; ++kt) {
        asm volatile("cp.async.wait_group 1;");
        __syncthreads();
        const float* As = sm + (kt % 3) * STAGE_F;
        const float* Ws = As + 4608;
#pragma unroll
        for (int kk = 0; kk < 32; kk += 8) {
            uint32_t af[4][4];
            uint32_t bf[7][2];
#pragma unroll
            for (int mt = 0; mt < 4; ++mt) {
                int r0 = wm * 64 + mt * 16 + (lane >> 2);
                int c0 = kk + (lane & 3);
                af[mt][0] = __float_as_uint(As[r0 * 36 + c0]);
                af[mt][1] = __float_as_uint(As[(r0 + 8) * 36 + c0]);
                af[mt][2] = __float_as_uint(As[r0 * 36 + c0 + 4]);
                af[mt][3] = __float_as_uint(As[(r0 + 8) * 36 + c0 + 4]);
            }
#pragma unroll
            for (int nt = 0; nt < 7; ++nt) {
                int n = wn * 56 + nt * 8 + (lane >> 2);
                int k = kk + (lane & 3);
                bf[nt][0] = __float_as_uint(Ws[n * 36 + k]);
                bf[nt][1] = __float_as_uint(Ws[n * 36 + k + 4]);
            }
#pragma unroll
            for (int mt = 0; mt < 4; ++mt)
#pragma unroll
                for (int nt = 0; nt < 7; ++nt)
                    mma_tf32(acc[mt][nt][0], acc[mt][nt][1], acc[mt][nt][2], acc[mt][nt][3],
                             af[mt][0], af[mt][1], af[mt][2], af[mt][3],
                             bf[nt][0], bf[nt][1]);
        }
        __syncthreads();
        if (kt + 2 < 126) load_tile(kt + 2, (kt + 2) % 3);
        else asm volatile("cp.async.commit_group;");
    }

#pragma unroll
    for (int mt = 0; mt < 4; ++mt) {
        int row = wm * 64 + mt * 16 + (lane >> 2);
#pragma unroll
        for (int nt = 0; nt < 7; ++nt) {
            long col = n0 + wn * 56 + nt * 8 + 2 * (lane & 3);
            float b0 = bias[col], b1 = bias[col + 1];
            float2 v0 = {fmaxf(acc[mt][nt][0] + b0, 0.f), fmaxf(acc[mt][nt][1] + b1, 0.f)};
            float2 v1 = {fmaxf(acc[mt][nt][2] + b0, 0.f), fmaxf(acc[mt][nt][3] + b1, 0.f)};
            *(float2*)&d_c[(long)row * NDIM + col] = v0;
            *(float2*)&d_c[(long)(row + 8) * NDIM + col] = v1;
        }
    }
}

// ---------------- k2: overlap-add to t-major c2t ----------------
__global__ void k_overlap() {
    int bc = blockIdx.x;           // b*32 + ch
    int b = bc >> 5, ch = bc & 31;
    int t = threadIdx.x;
    if (t >= L_) return;
    const float* cb = d_c + (long)b * NDIM + ch * (CK * P_);
    float s = 0.f;
#pragma unroll
    for (int k = 0; k < CK; k++) s += cb[k * (P_ + 1) + t];
    d_c2t[t * BCH + bc] = s;
}

// ---------------- k3: GRU1 (blocks 0..127) + skip GRU (blocks 128..143) ----
__global__ void __launch_bounds__(320, 1) k_gru(
    const float* __restrict__ g1Wih, const float* __restrict__ g1Whh,
    const float* __restrict__ g1bih, const float* __restrict__ g1bhh,
    const float* __restrict__ gsWih, const float* __restrict__ gsWhh,
    const float* __restrict__ gsbih, const float* __restrict__ gsbhh) {
    __shared__ __align__(16) float xs[L_ * HIDC];    // 5216 floats
    __shared__ __align__(16) float h_sh[104];
    __shared__ __align__(16) float s_sh[304];
    __shared__ __align__(16) float gi_sh[2][304];
    const int bid = blockIdx.x;
    const int j = threadIdx.x;

    if (bid < B_) {
        // ---- stage x[t][ch] for this batch row ----
        {
            uint32_t sb = (uint32_t)__cvta_generic_to_shared(xs);
            const float* src = d_c2t + bid * HIDC;
            for (int i = j; i < L_ * 8; i += 320) {
                int t = i >> 3, part = i & 7;
                asm volatile("cp.async.ca.shared.global [%0],[%1],16;" ::
                             "r"(sb + (uint32_t)(t * HIDC + part * 4) * 4),
                             "l"(src + (long)t * BCH + part * 4));
            }
            asm volatile("cp.async.commit_group;");
        }

        // ---- weights register-resident ----
        ull whh2[50], wih2[16];
        float bih_j = 0.f, bhh_j = 0.f;
        if (j < 300) {
            const ulonglong2* pw = (const ulonglong2*)(g1Whh + j * HIDR);
#pragma unroll
            for (int q = 0; q < 25; q++) { ulonglong2 v = pw[q]; whh2[2*q] = v.x; whh2[2*q+1] = v.y; }
            const ulonglong2* pi = (const ulonglong2*)(g1Wih + j * HIDC);
#pragma unroll
            for (int q = 0; q < 8; q++) { ulonglong2 v = pi[q]; wih2[2*q] = v.x; wih2[2*q+1] = v.y; }
            bih_j = g1bih[j]; bhh_j = g1bhh[j];
        }
        if (j < HIDR) h_sh[j] = 0.f;
        asm volatile("cp.async.wait_group 0;");
        __syncthreads();

        // ---- prologue: gi for t=0 ----
        if (j < 300) {
            const ulonglong2* xv = (const ulonglong2*)xs;
            ull g0 = pk2(bih_j, 0.f), g1v = pk2(0.f, 0.f);
#pragma unroll
            for (int q = 0; q < 8; q++) {
                ulonglong2 v = xv[q];
                g0 = fma2_(v.x, wih2[2*q], g0);
                g1v = fma2_(v.y, wih2[2*q+1], g1v);
            }
            float l0, h0, l1, h1;
            unpk2(g0, l0, h0); unpk2(g1v, l1, h1);
            gi_sh[0][j] = (l0 + h0) + (l1 + h1);
        }
        float h_reg = 0.f;
        __syncthreads();

        for (int t = 0; t < L_; ++t) {
            if (j < 300) {
                // gi for t+1 first (independent of h -> early MLP)
                ull g0, g1v;
                if (t + 1 < L_) {
                    const ulonglong2* xv = (const ulonglong2*)(xs + (t + 1) * HIDC);
                    g0 = pk2(bih_j, 0.f); g1v = pk2(0.f, 0.f);
#pragma unroll
                    for (int q = 0; q < 8; q++) {
                        ulonglong2 v = xv[q];
                        g0 = fma2_(v.x, wih2[2*q], g0);
                        g1v = fma2_(v.y, wih2[2*q+1], g1v);
                    }
                }
                // s_j = bhh_j + Whh_j . h   (4 accumulators)
                const ulonglong2* h2 = (const ulonglong2*)h_sh;
                ull a0 = pk2(bhh_j, 0.f), a1 = pk2(0.f, 0.f);
                ull a2 = pk2(0.f, 0.f),  a3 = pk2(0.f, 0.f);
#pragma unroll
                for (int q = 0; q < 25; q++) {
                    ulonglong2 hv = h2[q];
                    if (q & 1) {
                        a2 = fma2_(hv.x, whh2[2*q], a2);
                        a3 = fma2_(hv.y, whh2[2*q+1], a3);
                    } else {
                        a0 = fma2_(hv.x, whh2[2*q], a0);
                        a1 = fma2_(hv.y, whh2[2*q+1], a1);
                    }
                }
                float l0, h0, l1, h1, l2, h2f, l3, h3;
                unpk2(a0, l0, h0); unpk2(a1, l1, h1);
                unpk2(a2, l2, h2f); unpk2(a3, l3, h3);
                s_sh[j] = ((l0 + h0) + (l1 + h1)) + ((l2 + h2f) + (l3 + h3));
                if (t + 1 < L_) {
                    float gl0, gh0, gl1, gh1;
                    unpk2(g0, gl0, gh0); unpk2(g1v, gl1, gh1);
                    gi_sh[(t + 1) & 1][j] = (gl0 + gh0) + (gl1 + gh1);
                }
            }
            __syncthreads();
            if (j < HIDR) {
                const float* gi = gi_sh[t & 1];
                float r = sigm_a(gi[j] + s_sh[j]);
                float z = sigm_a(gi[j + 100] + s_sh[j + 100]);
                float n = tanh_ap(gi[j + 200] + r * s_sh[j + 200]);
                h_reg = z * (h_reg - n) + n;
                h_sh[j] = h_reg;
            }
            __syncthreads();
        }
        if (j < HIDR) d_h1[bid * HIDR + j] = h_reg;
    } else {
        // ---- skip GRU: 3072 sequences, one per thread, 6 steps ----
        float* ws = xs;  // reuse pool: Wih[480], Whh[75], bih[15], bhh[15]
        for (int i = j; i < 480; i += 320) ws[i] = gsWih[i];
        for (int i = j; i < 75; i += 320) ws[480 + i] = gsWhh[i];
        if (j < 15) { ws[555 + j] = gsbih[j]; ws[570 + j] = gsbhh[j]; }
        __syncthreads();
        if (j < 192) {
            int seq = (bid - B_) * 192 + j;        // = b*SKIP + sk
            int b = seq / SKIP, sk = seq % SKIP;
            float h[5] = {0.f, 0.f, 0.f, 0.f, 0.f};
            for (int pt = 0; pt < PT; ++pt) {
                const float4* xp = (const float4*)(d_c2t + (L_ - PT * SKIP + pt * SKIP + sk) * BCH + b * HIDC);
                float xv[32];
#pragma unroll
                for (int q = 0; q < 8; ++q) {
                    float4 v = xp[q];
                    xv[4*q] = v.x; xv[4*q+1] = v.y; xv[4*q+2] = v.z; xv[4*q+3] = v.w;
                }
                float gi[15], gh[15];
#pragma unroll
                for (int g = 0; g < 15; ++g) {
                    float a = ws[555 + g];
#pragma unroll
                    for (int i2 = 0; i2 < 32; ++i2) a += xv[i2] * ws[g * 32 + i2];
                    gi[g] = a;
                    float bg = ws[570 + g];
#pragma unroll
                    for (int i2 = 0; i2 < 5; ++i2) bg += h[i2] * ws[480 + g * 5 + i2];
                    gh[g] = bg;
                }
#pragma unroll
                for (int q = 0; q < 5; ++q) {
                    float r = sigm_a(gi[q] + gh[q]);
                    float z = sigm_a(gi[5 + q] + gh[5 + q]);
                    float n = tanh_ap(gi[10 + q] + r * gh[10 + q]);
                    h[q] = z * (h[q] - n) + n;
                }
            }
#pragma unroll
            for (int q = 0; q < 5; ++q) d_hs[seq * 5 + q] = h[q];
        }
    }
}

// ---------------- k4: final linear + highway + sigmoid (exact) ----------------
__global__ void k_fin(const float* __restrict__ x,
                      const float* __restrict__ lw, const float* __restrict__ lb,
                      const float* __restrict__ hww, const float* __restrict__ hwb,
                      float* __restrict__ out) {
    int b = blockIdx.x, m = threadIdx.x;
    if (m >= M_) return;
    const float* w = lw + m * (HIDR + SKIP * HIDS);
    float a = lb[m];
    const float* h1 = d_h1 + b * HIDR;
#pragma unroll 4
    for (int i = 0; i < HIDR; ++i) a += h1[i] * w[i];
    const float* hsp = d_hs + b * (SKIP * HIDS);
#pragma unroll 4
    for (int i = 0; i < SKIP * HIDS; ++i) a += hsp[i] * w[HIDR + i];
    float z = hwb[0];
#pragma unroll
    for (int wq = 0; wq < HW_; ++wq)
        z += x[b * KDIM + (P_ - HW_ + wq) * M_ + m] * hww[wq];
    out[b * M_ + m] = 1.f / (1.f + __expf(-(a + z)));
}

// ---------------- launch ----------------
extern "C" void kernel_launch(void* const* d_in, const int* in_sizes, int n_in,
                              void* d_out, int out_size) {
    const float* x       = (const float*)d_in[0];
    const float* conv_w  = (const float*)d_in[1];
    const float* conv_b  = (const float*)d_in[2];
    const float* g1Wih   = (const float*)d_in[3];
    const float* g1Whh   = (const float*)d_in[4];
    const float* g1bih   = (const float*)d_in[5];
    const float* g1bhh   = (const float*)d_in[6];
    const float* gsWih   = (const float*)d_in[7];
    const float* gsWhh   = (const float*)d_in[8];
    const float* gsbih   = (const float*)d_in[9];
    const float* gsbhh   = (const float*)d_in[10];
    const float* lin1_w  = (const float*)d_in[11];
    const float* lin1_b  = (const float*)d_in[12];
    const float* hw_w    = (const float*)d_in[13];
    const float* hw_b    = (const float*)d_in[14];
    float* out = (float*)d_out;

    cudaFuncSetAttribute(k_gemm, cudaFuncAttributeMaxDynamicSharedMemorySize, 3 * STAGE_F * 4);

    k_cvt<<<(B_ * KDIM + 255) / 256, 256>>>(x);
    k_gemm<<<NDIM / BN_, 256, 3 * STAGE_F * 4>>>(conv_w, conv_b);
    k_overlap<<<BCH, 192>>>();
    k_gru<<<B_ + 16, 320>>>(g1Wih, g1Whh, g1bih, g1bhh, gsWih, gsWhh, gsbih, gsbhh);
    k_fin<<<B_, 32>>>(x, lin1_w, lin1_b, hw_w, hw_b, out);
}